// round 15
// baseline (speedup 1.0000x reference)
#include <cuda_runtime.h>
#include <cuda_bf16.h>
#include <cstdint>
#include <math.h>

// Problem constants
#define B_ 2
#define S_ 2048
#define D_ 1024
#define H_ 16
#define DH_ 64
#define BS_ (B_ * S_)
#define INV_SQRT_DH 0.125f
#define NKT64 (S_ / 64)         // 32 key tiles of 64
#define C1 0.3606738f           // 0.25 * log2(e)  (score scale folded into exp2)
#define LOG2E 1.4426950f

// Scratch (device globals: no runtime allocation allowed)
__device__ float g_Q[BS_ * D_];            // q projection fp32, [B,S,H,DH]
__device__ __nv_bfloat16 g_Qbf[BS_ * D_];  // q bf16, head-major [B,H,S,DH]
__device__ float g_attn[BS_ * D_];         // O/l, [B,S,H,DH]
__device__ float g_M[H_ * DH_ * DH_];      // per-head 64x64 (incl. 1/sqrt(dh))
__device__ float g_Wt[D_ * D_];            // folded W_out @ M  ([n][h*64+d])
__device__ float g_kb2[B_ * H_ * S_];      // log2e * (mask ? -||q_t||^2/8 : -9e15)

// ===========================================================================
// Warp-level bf16 MMA (sm_80+ PTX; HMMA fallback pipe on sm_103)
// D(16x8,f32) += A(16x16,bf16,row) * B(16x8,bf16,col)
// ===========================================================================
__device__ __forceinline__ void mma16816(float c[4], const uint32_t a[4],
                                         uint32_t b0, uint32_t b1) {
    asm volatile(
        "mma.sync.aligned.m16n8k16.row.col.f32.bf16.bf16.f32 "
        "{%0,%1,%2,%3}, {%4,%5,%6,%7}, {%8,%9}, {%0,%1,%2,%3};"
        : "+f"(c[0]), "+f"(c[1]), "+f"(c[2]), "+f"(c[3])
        : "r"(a[0]), "r"(a[1]), "r"(a[2]), "r"(a[3]), "r"(b0), "r"(b1));
}
__device__ __forceinline__ float ex2f(float x) {
    float r;
    asm("ex2.approx.f32 %0, %1;" : "=f"(r) : "f"(x));
    return r;
}
__device__ __forceinline__ uint32_t packbf2(float x, float y) {
    __nv_bfloat162 p = __floats2bfloat162_rn(x, y);
    return *(uint32_t*)&p;
}

// ===========================================================================
// Dense GEMM: C = A @ W^T + bias (+R).  128x128 tile, BK=16, 8x8 microtile.
// ===========================================================================
template <bool RESID>
__global__ __launch_bounds__(256, 2) void gemm_xwT(
    const float* __restrict__ A, const float* __restrict__ W,
    const float* __restrict__ bias, const float* __restrict__ R,
    float* __restrict__ C, int M, int N, int K)
{
    __shared__ float As[2][16][132];
    __shared__ float Ws[2][16][132];
    const int tid = threadIdx.x;
    const int tx = tid & 15, ty = tid >> 4;
    const int m0 = blockIdx.y * 128, n0 = blockIdx.x * 128;
    const int lr = tid >> 2, lk = (tid & 3) * 4;

    float4 ar[2], wr[2];
#pragma unroll
    for (int e = 0; e < 2; e++) {
        ar[e] = *(const float4*)&A[(size_t)(m0 + lr + 64 * e) * K + lk];
        wr[e] = *(const float4*)&W[(size_t)(n0 + lr + 64 * e) * K + lk];
    }
#pragma unroll
    for (int e = 0; e < 2; e++) {
        As[0][lk + 0][lr + 64 * e] = ar[e].x; As[0][lk + 1][lr + 64 * e] = ar[e].y;
        As[0][lk + 2][lr + 64 * e] = ar[e].z; As[0][lk + 3][lr + 64 * e] = ar[e].w;
        Ws[0][lk + 0][lr + 64 * e] = wr[e].x; Ws[0][lk + 1][lr + 64 * e] = wr[e].y;
        Ws[0][lk + 2][lr + 64 * e] = wr[e].z; Ws[0][lk + 3][lr + 64 * e] = wr[e].w;
    }
    __syncthreads();

    float acc[8][8] = {};
    const int nk = K / 16;
    for (int t = 0; t < nk; t++) {
        const int cur = t & 1;
        if (t + 1 < nk) {
#pragma unroll
            for (int e = 0; e < 2; e++) {
                ar[e] = *(const float4*)&A[(size_t)(m0 + lr + 64 * e) * K + (t + 1) * 16 + lk];
                wr[e] = *(const float4*)&W[(size_t)(n0 + lr + 64 * e) * K + (t + 1) * 16 + lk];
            }
        }
#pragma unroll
        for (int kk = 0; kk < 16; kk++) {
            float4 a0 = *(const float4*)&As[cur][kk][ty * 8];
            float4 a1 = *(const float4*)&As[cur][kk][ty * 8 + 4];
            float4 b0 = *(const float4*)&Ws[cur][kk][tx * 8];
            float4 b1 = *(const float4*)&Ws[cur][kk][tx * 8 + 4];
            float av[8] = {a0.x, a0.y, a0.z, a0.w, a1.x, a1.y, a1.z, a1.w};
            float bv[8] = {b0.x, b0.y, b0.z, b0.w, b1.x, b1.y, b1.z, b1.w};
#pragma unroll
            for (int i = 0; i < 8; i++)
#pragma unroll
                for (int j = 0; j < 8; j++) acc[i][j] = fmaf(av[i], bv[j], acc[i][j]);
        }
        if (t + 1 < nk) {
            const int nxt = cur ^ 1;
#pragma unroll
            for (int e = 0; e < 2; e++) {
                As[nxt][lk + 0][lr + 64 * e] = ar[e].x; As[nxt][lk + 1][lr + 64 * e] = ar[e].y;
                As[nxt][lk + 2][lr + 64 * e] = ar[e].z; As[nxt][lk + 3][lr + 64 * e] = ar[e].w;
                Ws[nxt][lk + 0][lr + 64 * e] = wr[e].x; Ws[nxt][lk + 1][lr + 64 * e] = wr[e].y;
                Ws[nxt][lk + 2][lr + 64 * e] = wr[e].z; Ws[nxt][lk + 3][lr + 64 * e] = wr[e].w;
            }
            __syncthreads();
        }
    }

    float4 bb0 = *(const float4*)&bias[n0 + tx * 8];
    float4 bb1 = *(const float4*)&bias[n0 + tx * 8 + 4];
    float bv[8] = {bb0.x, bb0.y, bb0.z, bb0.w, bb1.x, bb1.y, bb1.z, bb1.w};
#pragma unroll
    for (int i = 0; i < 8; i++) {
        const size_t row = (size_t)(m0 + ty * 8 + i) * N + n0 + tx * 8;
        float o[8];
#pragma unroll
        for (int j = 0; j < 8; j++) o[j] = acc[i][j] + bv[j];
        if (RESID) {
            float4 r0 = *(const float4*)&R[row];
            float4 r1 = *(const float4*)&R[row + 4];
            o[0] += r0.x; o[1] += r0.y; o[2] += r0.z; o[3] += r0.w;
            o[4] += r1.x; o[5] += r1.y; o[6] += r1.z; o[7] += r1.w;
        }
        *(float4*)&C[row]     = make_float4(o[0], o[1], o[2], o[3]);
        *(float4*)&C[row + 4] = make_float4(o[4], o[5], o[6], o[7]);
    }
}

// ===========================================================================
// M_h[d][f] = sum_e W_q[e, h*64+d] * W_v[e, h*64+f] * 0.125
// ===========================================================================
__global__ __launch_bounds__(256) void compute_M_kernel(
    const float* __restrict__ Wq, const float* __restrict__ Wv)
{
    __shared__ float Aq[32][68];
    __shared__ float Av[32][68];
    const int h = blockIdx.x;
    const int tid = threadIdx.x;
    const int tx = tid & 15, ty = tid >> 4;

    float acc[4][4] = {};
    for (int e0 = 0; e0 < D_; e0 += 32) {
#pragma unroll
        for (int e = 0; e < 8; e++) {
            int idx = tid + e * 256;
            int ee = idx >> 6, c = idx & 63;
            Aq[ee][c] = Wq[(size_t)(e0 + ee) * D_ + h * DH_ + c];
            Av[ee][c] = Wv[(size_t)(e0 + ee) * D_ + h * DH_ + c];
        }
        __syncthreads();
#pragma unroll
        for (int ee = 0; ee < 32; ee++) {
            float4 a4 = *(const float4*)&Aq[ee][ty * 4];
            float4 b4 = *(const float4*)&Av[ee][tx * 4];
            float av[4] = {a4.x, a4.y, a4.z, a4.w};
            float bv[4] = {b4.x, b4.y, b4.z, b4.w};
#pragma unroll
            for (int i = 0; i < 4; i++)
#pragma unroll
                for (int j = 0; j < 4; j++) acc[i][j] += av[i] * bv[j];
        }
        __syncthreads();
    }
#pragma unroll
    for (int i = 0; i < 4; i++)
#pragma unroll
        for (int j = 0; j < 4; j++)
            g_M[h * DH_ * DH_ + (ty * 4 + i) * DH_ + tx * 4 + j] = acc[i][j] * INV_SQRT_DH;
}

// ===========================================================================
// Fold: Wt[n, h*64+d] = sum_f W_out[n, h*64+f] * M_h[d][f]
// ===========================================================================
__global__ __launch_bounds__(256) void fold_wout_kernel(const float* __restrict__ Wout)
{
    __shared__ float Msm[64][68];   // [f][d]
    const int h = blockIdx.x & 15;
    const int n0 = (blockIdx.x >> 4) * 64;
    const int tid = threadIdx.x;

#pragma unroll
    for (int e = 0; e < 16; e++) {
        int i = tid + e * 256;
        int f = i & 63, d = i >> 6;
        Msm[f][d] = g_M[h * 4096 + d * 64 + f];
    }
    __syncthreads();

    const int n = n0 + (tid >> 2), dg = (tid & 3) * 16;
    float acc[16] = {};
    const float* wrow = Wout + (size_t)n * D_ + h * 64;
    for (int f = 0; f < 64; f++) {
        float wv = wrow[f];
#pragma unroll
        for (int q = 0; q < 4; q++) {
            float4 m4 = *(const float4*)&Msm[f][dg + q * 4];
            acc[q * 4 + 0] = fmaf(wv, m4.x, acc[q * 4 + 0]);
            acc[q * 4 + 1] = fmaf(wv, m4.y, acc[q * 4 + 1]);
            acc[q * 4 + 2] = fmaf(wv, m4.z, acc[q * 4 + 2]);
            acc[q * 4 + 3] = fmaf(wv, m4.w, acc[q * 4 + 3]);
        }
    }
    float* dst = g_Wt + (size_t)n * D_ + h * 64 + dg;
#pragma unroll
    for (int q = 0; q < 4; q++)
        *(float4*)&dst[q * 4] = make_float4(acc[q*4], acc[q*4+1], acc[q*4+2], acc[q*4+3]);
}

// ===========================================================================
// Convert: g_Q [B,S,H,DH] fp32 -> g_Qbf [B,H,S,DH] bf16; kb2 = log2e * bias
// ===========================================================================
__global__ __launch_bounds__(256) void convert_q_kernel(const int* __restrict__ mask)
{
    const int idx = blockIdx.x * 256 + threadIdx.x;   // 0..65535
    const int s = idx & (S_ - 1);
    const int bh = idx >> 11;
    const int b = bh >> 4, h = bh & 15;
    const float* src = g_Q + (size_t)(b * S_ + s) * D_ + h * DH_;
    float sq = 0.0f;
    uint32_t u[32];
#pragma unroll
    for (int j = 0; j < 64; j += 4) {
        float4 v = *(const float4*)&src[j];
        sq += v.x * v.x + v.y * v.y + v.z * v.z + v.w * v.w;
        u[j / 2]     = packbf2(v.x, v.y);
        u[j / 2 + 1] = packbf2(v.z, v.w);
    }
    uint4* dst = (uint4*)(g_Qbf + (size_t)(bh * S_ + s) * DH_);
#pragma unroll
    for (int e = 0; e < 8; e++)
        dst[e] = make_uint4(u[e*4], u[e*4+1], u[e*4+2], u[e*4+3]);
    const float kb = -sq * INV_SQRT_DH;
    g_kb2[bh * S_ + s] = (mask[b * S_ + s] == 0) ? -1.3e16f : kb * LOG2E;
}

// ===========================================================================
// Flash attention on warp-level bf16 HMMA.  Block = (b,h) x 128-query tile.
// 8 warps x 16 query rows; Bc=64 keys/iter.  p = exp2(C1*S + kb2), no row max.
// K tile kept in both [t][d] (QK B-frags) and [d][t] (PV B-frags; V = K).
// P never leaves registers (S C-frag layout == PV A-frag layout).
// ===========================================================================
__global__ __launch_bounds__(256, 2) void attn_kernel()
{
    __shared__ __align__(16) __nv_bfloat16 sKtd[2][64][72];  // [t][d], stride 144B
    __shared__ __align__(16) __nv_bfloat16 sKdt[2][64][72];  // [d][t]
    __shared__ float kb_sm[2][64];

    const int tid = threadIdx.x;
    const int wid = tid >> 5, lane = tid & 31;
    const int lg = lane >> 2;        // fragment row group 0..7
    const int qc = (lane & 3) * 2;   // fragment col pair base
    const int qt = blockIdx.x;
    const int bh = blockIdx.y;
    const int b = bh >> 4, h = bh & 15;
    const __nv_bfloat16* Qbf = g_Qbf + (size_t)bh * S_ * DH_;
    const float* kb2 = g_kb2 + bh * S_;

    // Q A-fragments (held in registers for all iterations)
    const int r0 = qt * 128 + wid * 16 + lg;
    uint32_t qa[4][4];
#pragma unroll
    for (int k = 0; k < 4; k++) {
        qa[k][0] = *(const uint32_t*)&Qbf[(size_t)r0 * DH_ + k * 16 + qc];
        qa[k][1] = *(const uint32_t*)&Qbf[(size_t)(r0 + 8) * DH_ + k * 16 + qc];
        qa[k][2] = *(const uint32_t*)&Qbf[(size_t)r0 * DH_ + k * 16 + qc + 8];
        qa[k][3] = *(const uint32_t*)&Qbf[(size_t)(r0 + 8) * DH_ + k * 16 + qc + 8];
    }

    // K loader mapping: row t = tid>>2, d block = (tid&3)*16 (32B per thread)
    const int lt = tid >> 2, ldd = (tid & 3) * 16;

    // Prologue: stage K(0), kb(0) into buffer 0
    {
        const __nv_bfloat16* src = Qbf + (size_t)lt * DH_ + ldd;
        uint4 v0 = *(const uint4*)src;
        uint4 v1 = *(const uint4*)(src + 8);
        *(uint4*)&sKtd[0][lt][ldd]     = v0;
        *(uint4*)&sKtd[0][lt][ldd + 8] = v1;
        const __nv_bfloat16* e0 = (const __nv_bfloat16*)&v0;
        const __nv_bfloat16* e1 = (const __nv_bfloat16*)&v1;
#pragma unroll
        for (int i = 0; i < 8; i++) {
            sKdt[0][ldd + i][lt]     = e0[i];
            sKdt[0][ldd + 8 + i][lt] = e1[i];
        }
        if (tid < 64) kb_sm[0][tid] = kb2[tid];
    }
    __syncthreads();

    float lacc0 = 0.0f, lacc1 = 0.0f;
    float oacc[8][4] = {};

    for (int kt = 0; kt < NKT64; kt++) {
        const int buf = kt & 1;
        const bool pf = (kt + 1 < NKT64);
        uint4 v0, v1;
        float kbv = 0.0f;
        if (pf) {
            const __nv_bfloat16* src = Qbf + (size_t)((kt + 1) * 64 + lt) * DH_ + ldd;
            v0 = *(const uint4*)src;
            v1 = *(const uint4*)(src + 8);
            if (tid < 64) kbv = kb2[(kt + 1) * 64 + tid];
        }

        // ---- S = Q @ K^T : 8 n-tiles (8 keys each) x 4 k-steps ----
        float sc[8][4];
#pragma unroll
        for (int nt = 0; nt < 8; nt++) {
            sc[nt][0] = sc[nt][1] = sc[nt][2] = sc[nt][3] = 0.0f;
#pragma unroll
            for (int k = 0; k < 4; k++) {
                uint32_t b0 = *(const uint32_t*)&sKtd[buf][nt * 8 + lg][k * 16 + qc];
                uint32_t b1 = *(const uint32_t*)&sKtd[buf][nt * 8 + lg][k * 16 + qc + 8];
                mma16816(sc[nt], qa[k], b0, b1);
            }
        }

        // ---- softmax: p = exp2(C1*s + kb2[t]); accumulate l; pack bf16 ----
        uint32_t pk[8][2];
#pragma unroll
        for (int nt = 0; nt < 8; nt++) {
            float2 kbp = *(const float2*)&kb_sm[buf][nt * 8 + qc];
            float p0 = ex2f(fmaf(sc[nt][0], C1, kbp.x));
            float p1 = ex2f(fmaf(sc[nt][1], C1, kbp.y));
            float p2 = ex2f(fmaf(sc[nt][2], C1, kbp.x));
            float p3 = ex2f(fmaf(sc[nt][3], C1, kbp.y));
            lacc0 += p0 + p1;
            lacc1 += p2 + p3;
            pk[nt][0] = packbf2(p0, p1);
            pk[nt][1] = packbf2(p2, p3);
        }

        // ---- O += P @ K : A-frags from pk (C layout == A layout trick) ----
#pragma unroll
        for (int tk = 0; tk < 4; tk++) {
            uint32_t pa[4] = {pk[2 * tk][0], pk[2 * tk][1],
                              pk[2 * tk + 1][0], pk[2 * tk + 1][1]};
#pragma unroll
            for (int nt = 0; nt < 8; nt++) {
                uint32_t b0 = *(const uint32_t*)&sKdt[buf][nt * 8 + lg][tk * 16 + qc];
                uint32_t b1 = *(const uint32_t*)&sKdt[buf][nt * 8 + lg][tk * 16 + qc + 8];
                mma16816(oacc[nt], pa, b0, b1);
            }
        }

        // ---- commit prefetched K(kt+1) into the other buffer ----
        if (pf) {
            const int nb = buf ^ 1;
            *(uint4*)&sKtd[nb][lt][ldd]     = v0;
            *(uint4*)&sKtd[nb][lt][ldd + 8] = v1;
            const __nv_bfloat16* e0 = (const __nv_bfloat16*)&v0;
            const __nv_bfloat16* e1 = (const __nv_bfloat16*)&v1;
#pragma unroll
            for (int i = 0; i < 8; i++) {
                sKdt[nb][ldd + i][lt]     = e0[i];
                sKdt[nb][ldd + 8 + i][lt] = e1[i];
            }
            if (tid < 64) kb_sm[nb][tid] = kbv;
        }
        __syncthreads();
    }

    // ---- epilogue: O / l -> g_attn ----
    lacc0 += __shfl_xor_sync(0xffffffffu, lacc0, 1);
    lacc0 += __shfl_xor_sync(0xffffffffu, lacc0, 2);
    lacc1 += __shfl_xor_sync(0xffffffffu, lacc1, 1);
    lacc1 += __shfl_xor_sync(0xffffffffu, lacc1, 2);
    const float inv0 = 1.0f / lacc0;
    const float inv1 = 1.0f / lacc1;

    const size_t grow0 = (size_t)(b * S_ + qt * 128 + wid * 16 + lg) * D_ + h * DH_;
    const size_t grow1 = grow0 + 8 * D_;
#pragma unroll
    for (int nt = 0; nt < 8; nt++) {
        const int d = nt * 8 + qc;
        *(float2*)&g_attn[grow0 + d] = make_float2(oacc[nt][0] * inv0, oacc[nt][1] * inv0);
        *(float2*)&g_attn[grow1 + d] = make_float2(oacc[nt][2] * inv1, oacc[nt][3] * inv1);
    }
}

// ===========================================================================
// Launch
// ===========================================================================
extern "C" void kernel_launch(void* const* d_in, const int* in_sizes, int n_in,
                              void* d_out, int out_size)
{
    // metadata order: x, W_q, b_q, W_v, W_out, b_out, mask
    const float* x     = (const float*)d_in[0];
    const float* W_q   = (const float*)d_in[1];
    const float* b_q   = (const float*)d_in[2];
    const float* W_v   = (const float*)d_in[3];
    const float* W_out = (const float*)d_in[4];
    const float* b_out = (const float*)d_in[5];
    const int*   mask  = (const int*)d_in[6];
    float* out = (float*)d_out;

    float *pQ, *pA, *pWt;
    cudaGetSymbolAddress((void**)&pQ,  g_Q);
    cudaGetSymbolAddress((void**)&pA,  g_attn);
    cudaGetSymbolAddress((void**)&pWt, g_Wt);

    dim3 gge(D_ / 128, BS_ / 128);

    // 1) Q = x @ W_q^T + b_q (fp32)
    gemm_xwT<false><<<gge, 256>>>(x, W_q, b_q, nullptr, pQ, BS_, D_, D_);

    // 2) bf16 head-major Q + per-key bias
    convert_q_kernel<<<(BS_ * H_) / 256, 256>>>(mask);

    // 3) per-head M, folded into W_out
    compute_M_kernel<<<H_, 256>>>(W_q, W_v);
    fold_wout_kernel<<<H_ * (D_ / 64), 256>>>(W_out);

    // 4) attention (warp-level bf16 HMMA flash)
    attn_kernel<<<dim3(S_ / 128, B_ * H_), 256>>>();

    // 5) out = x + (O/l) @ Wt^T + b_out
    gemm_xwT<true><<<gge, 256>>>(pA, pWt, b_out, x, out, BS_, D_, D_);
}

// round 16
// speedup vs baseline: 1.8687x; 1.8687x over previous
#include <cuda_runtime.h>
#include <cuda_bf16.h>
#include <cstdint>
#include <math.h>

// Problem constants
#define B_ 2
#define S_ 2048
#define D_ 1024
#define H_ 16
#define DH_ 64
#define BS_ (B_ * S_)
#define INV_SQRT_DH 0.125f
#define NKT64 (S_ / 64)         // 32 key tiles of 64
#define C1 0.3606738f           // 0.25 * log2(e)  (score scale folded into exp2)
#define LOG2E 1.4426950f

// Scratch (device globals: no runtime allocation allowed)
__device__ float g_Q[BS_ * D_];            // q projection fp32, [B,S,H,DH]
__device__ __nv_bfloat16 g_Qbf[BS_ * D_];  // q bf16, head-major [B,H,S,DH]
__device__ float g_attn[BS_ * D_];         // O/l, [B,S,H,DH]
__device__ float g_M[H_ * DH_ * DH_];      // per-head 64x64 (incl. 1/sqrt(dh))
__device__ float g_Wt[D_ * D_];            // folded W_out @ M  ([n][h*64+d])
__device__ float g_kb2[B_ * H_ * S_];      // log2e * (mask ? -||q_t||^2/8 : -9e15)

// ===========================================================================
// Warp-level bf16 MMA + helpers (sm_80+ PTX; HMMA pipe on sm_103)
// ===========================================================================
__device__ __forceinline__ void mma16816(float c[4], const uint32_t a[4],
                                         uint32_t b0, uint32_t b1) {
    asm volatile(
        "mma.sync.aligned.m16n8k16.row.col.f32.bf16.bf16.f32 "
        "{%0,%1,%2,%3}, {%4,%5,%6,%7}, {%8,%9}, {%0,%1,%2,%3};"
        : "+f"(c[0]), "+f"(c[1]), "+f"(c[2]), "+f"(c[3])
        : "r"(a[0]), "r"(a[1]), "r"(a[2]), "r"(a[3]), "r"(b0), "r"(b1));
}
__device__ __forceinline__ float ex2f(float x) {
    float r;
    asm("ex2.approx.f32 %0, %1;" : "=f"(r) : "f"(x));
    return r;
}
__device__ __forceinline__ uint32_t packbf2(float x, float y) {
    __nv_bfloat162 p = __floats2bfloat162_rn(x, y);
    return *(uint32_t*)&p;
}
__device__ __forceinline__ uint32_t smem_u32(const void* p) {
    uint32_t a;
    asm("{ .reg .u64 t; cvta.to.shared.u64 t, %1; cvt.u32.u64 %0, t; }" : "=r"(a) : "l"(p));
    return a;
}
__device__ __forceinline__ void ldmx4(uint32_t r[4], uint32_t addr) {
    asm volatile("ldmatrix.sync.aligned.m8n8.x4.shared.b16 {%0,%1,%2,%3}, [%4];"
                 : "=r"(r[0]), "=r"(r[1]), "=r"(r[2]), "=r"(r[3]) : "r"(addr));
}
__device__ __forceinline__ void ldmx2(uint32_t& r0, uint32_t& r1, uint32_t addr) {
    asm volatile("ldmatrix.sync.aligned.m8n8.x2.shared.b16 {%0,%1}, [%2];"
                 : "=r"(r0), "=r"(r1) : "r"(addr));
}

// ===========================================================================
// bf16 tensor-core GEMM: C = A @ W^T + bias (+R).  A:[M,K], W:[N,K] fp32.
// 128x128 tile, BK=16, 256 threads (8 warps = 2m x 4n), warp tile 64x32.
// fp32 gmem -> bf16 smem inline. Stride 24 bf16 => conflict-free ldmatrix.
// ===========================================================================
#define GSTR 24
#define GBUF (128 * GSTR * 2)   // bytes per buffer per matrix

template <bool RESID>
__global__ __launch_bounds__(256, 2) void gemm_bf16(
    const float* __restrict__ A, const float* __restrict__ W,
    const float* __restrict__ bias, const float* __restrict__ R,
    float* __restrict__ C, int M, int N, int K)
{
    __shared__ __align__(16) __nv_bfloat16 As[2][128][GSTR];
    __shared__ __align__(16) __nv_bfloat16 Ws[2][128][GSTR];

    const int tid = threadIdx.x, lane = tid & 31, wid = tid >> 5;
    const int wm = (wid >> 2) * 64, wn = (wid & 3) * 32;
    const int lg = lane >> 2, qc = (lane & 3) * 2;
    const int m0 = blockIdx.y * 128, n0 = blockIdx.x * 128;
    const int lrow = tid >> 1, lpart = (tid & 1) * 8;   // loader: half-row each

    const uint32_t aSm = smem_u32(&As[0][0][0]);
    const uint32_t bSm = smem_u32(&Ws[0][0][0]);
    // ldmatrix lane addresses (bytes)
    const uint32_t aFrag = aSm + (uint32_t)(((wm + (lane & 15)) * GSTR + (lane >> 4) * 8) * 2);
    const uint32_t bFrag = bSm + (uint32_t)(((wn + (lane & 7)) * GSTR + ((lane >> 3) & 1) * 8) * 2);

    // ---- preload tile 0 ----
    {
        const float* ap = &A[(size_t)(m0 + lrow) * K + lpart];
        const float* wp = &W[(size_t)(n0 + lrow) * K + lpart];
        float4 a0 = *(const float4*)ap, a1 = *(const float4*)(ap + 4);
        float4 w0 = *(const float4*)wp, w1 = *(const float4*)(wp + 4);
        *(uint4*)&As[0][lrow][lpart] = make_uint4(packbf2(a0.x, a0.y), packbf2(a0.z, a0.w),
                                                  packbf2(a1.x, a1.y), packbf2(a1.z, a1.w));
        *(uint4*)&Ws[0][lrow][lpart] = make_uint4(packbf2(w0.x, w0.y), packbf2(w0.z, w0.w),
                                                  packbf2(w1.x, w1.y), packbf2(w1.z, w1.w));
    }
    __syncthreads();

    float acc[4][4][4] = {};   // [mt][nt][frag]
    const int nk = K / 16;
    for (int t = 0; t < nk; t++) {
        const int buf = t & 1;
        float4 a0, a1, w0, w1;
        const bool pf = (t + 1 < nk);
        if (pf) {
            const float* ap = &A[(size_t)(m0 + lrow) * K + (t + 1) * 16 + lpart];
            const float* wp = &W[(size_t)(n0 + lrow) * K + (t + 1) * 16 + lpart];
            a0 = *(const float4*)ap; a1 = *(const float4*)(ap + 4);
            w0 = *(const float4*)wp; w1 = *(const float4*)(wp + 4);
        }

        // ---- fragments + 16 MMAs ----
        uint32_t af[4][4];
#pragma unroll
        for (int mt = 0; mt < 4; mt++)
            ldmx4(af[mt], aFrag + buf * GBUF + mt * (16 * GSTR * 2));
        uint32_t bf[4][2];
#pragma unroll
        for (int nt = 0; nt < 4; nt++)
            ldmx2(bf[nt][0], bf[nt][1], bFrag + buf * GBUF + nt * (8 * GSTR * 2));
#pragma unroll
        for (int mt = 0; mt < 4; mt++)
#pragma unroll
            for (int nt = 0; nt < 4; nt++)
                mma16816(acc[mt][nt], af[mt], bf[nt][0], bf[nt][1]);

        if (pf) {
            const int nb = buf ^ 1;
            *(uint4*)&As[nb][lrow][lpart] = make_uint4(packbf2(a0.x, a0.y), packbf2(a0.z, a0.w),
                                                       packbf2(a1.x, a1.y), packbf2(a1.z, a1.w));
            *(uint4*)&Ws[nb][lrow][lpart] = make_uint4(packbf2(w0.x, w0.y), packbf2(w0.z, w0.w),
                                                       packbf2(w1.x, w1.y), packbf2(w1.z, w1.w));
        }
        __syncthreads();
    }

    // ---- epilogue ----
#pragma unroll
    for (int nt = 0; nt < 4; nt++) {
        const int col = n0 + wn + nt * 8 + qc;
        const float2 b2 = *(const float2*)&bias[col];
#pragma unroll
        for (int mt = 0; mt < 4; mt++) {
            const int row = m0 + wm + mt * 16 + lg;
            float2 o0 = make_float2(acc[mt][nt][0] + b2.x, acc[mt][nt][1] + b2.y);
            float2 o1 = make_float2(acc[mt][nt][2] + b2.x, acc[mt][nt][3] + b2.y);
            if (RESID) {
                float2 r0 = *(const float2*)&R[(size_t)row * N + col];
                float2 r1 = *(const float2*)&R[(size_t)(row + 8) * N + col];
                o0.x += r0.x; o0.y += r0.y; o1.x += r1.x; o1.y += r1.y;
            }
            *(float2*)&C[(size_t)row * N + col]       = o0;
            *(float2*)&C[(size_t)(row + 8) * N + col] = o1;
        }
    }
}

// ===========================================================================
// M_h[d][f] = sum_e W_q[e, h*64+d] * W_v[e, h*64+f] * 0.125
// ===========================================================================
__global__ __launch_bounds__(256) void compute_M_kernel(
    const float* __restrict__ Wq, const float* __restrict__ Wv)
{
    __shared__ float Aq[32][68];
    __shared__ float Av[32][68];
    const int h = blockIdx.x;
    const int tid = threadIdx.x;
    const int tx = tid & 15, ty = tid >> 4;

    float acc[4][4] = {};
    for (int e0 = 0; e0 < D_; e0 += 32) {
#pragma unroll
        for (int e = 0; e < 8; e++) {
            int idx = tid + e * 256;
            int ee = idx >> 6, c = idx & 63;
            Aq[ee][c] = Wq[(size_t)(e0 + ee) * D_ + h * DH_ + c];
            Av[ee][c] = Wv[(size_t)(e0 + ee) * D_ + h * DH_ + c];
        }
        __syncthreads();
#pragma unroll
        for (int ee = 0; ee < 32; ee++) {
            float4 a4 = *(const float4*)&Aq[ee][ty * 4];
            float4 b4 = *(const float4*)&Av[ee][tx * 4];
            float av[4] = {a4.x, a4.y, a4.z, a4.w};
            float bv[4] = {b4.x, b4.y, b4.z, b4.w};
#pragma unroll
            for (int i = 0; i < 4; i++)
#pragma unroll
                for (int j = 0; j < 4; j++) acc[i][j] += av[i] * bv[j];
        }
        __syncthreads();
    }
#pragma unroll
    for (int i = 0; i < 4; i++)
#pragma unroll
        for (int j = 0; j < 4; j++)
            g_M[h * DH_ * DH_ + (ty * 4 + i) * DH_ + tx * 4 + j] = acc[i][j] * INV_SQRT_DH;
}

// ===========================================================================
// Fold: Wt[n, h*64+d] = sum_f W_out[n, h*64+f] * M_h[d][f]
// ===========================================================================
__global__ __launch_bounds__(256) void fold_wout_kernel(const float* __restrict__ Wout)
{
    __shared__ float Msm[64][68];   // [f][d]
    const int h = blockIdx.x & 15;
    const int n0 = (blockIdx.x >> 4) * 64;
    const int tid = threadIdx.x;

#pragma unroll
    for (int e = 0; e < 16; e++) {
        int i = tid + e * 256;
        int f = i & 63, d = i >> 6;
        Msm[f][d] = g_M[h * 4096 + d * 64 + f];
    }
    __syncthreads();

    const int n = n0 + (tid >> 2), dg = (tid & 3) * 16;
    float acc[16] = {};
    const float* wrow = Wout + (size_t)n * D_ + h * 64;
    for (int f = 0; f < 64; f++) {
        float wv = wrow[f];
#pragma unroll
        for (int q = 0; q < 4; q++) {
            float4 m4 = *(const float4*)&Msm[f][dg + q * 4];
            acc[q * 4 + 0] = fmaf(wv, m4.x, acc[q * 4 + 0]);
            acc[q * 4 + 1] = fmaf(wv, m4.y, acc[q * 4 + 1]);
            acc[q * 4 + 2] = fmaf(wv, m4.z, acc[q * 4 + 2]);
            acc[q * 4 + 3] = fmaf(wv, m4.w, acc[q * 4 + 3]);
        }
    }
    float* dst = g_Wt + (size_t)n * D_ + h * 64 + dg;
#pragma unroll
    for (int q = 0; q < 4; q++)
        *(float4*)&dst[q * 4] = make_float4(acc[q*4], acc[q*4+1], acc[q*4+2], acc[q*4+3]);
}

// ===========================================================================
// Convert: g_Q [B,S,H,DH] fp32 -> g_Qbf [B,H,S,DH] bf16; kb2 = log2e * bias
// ===========================================================================
__global__ __launch_bounds__(256) void convert_q_kernel(const int* __restrict__ mask)
{
    const int idx = blockIdx.x * 256 + threadIdx.x;   // 0..65535
    const int s = idx & (S_ - 1);
    const int bh = idx >> 11;
    const int b = bh >> 4, h = bh & 15;
    const float* src = g_Q + (size_t)(b * S_ + s) * D_ + h * DH_;
    float sq = 0.0f;
    uint32_t u[32];
#pragma unroll
    for (int j = 0; j < 64; j += 4) {
        float4 v = *(const float4*)&src[j];
        sq += v.x * v.x + v.y * v.y + v.z * v.z + v.w * v.w;
        u[j / 2]     = packbf2(v.x, v.y);
        u[j / 2 + 1] = packbf2(v.z, v.w);
    }
    uint4* dst = (uint4*)(g_Qbf + (size_t)(bh * S_ + s) * DH_);
#pragma unroll
    for (int e = 0; e < 8; e++)
        dst[e] = make_uint4(u[e*4], u[e*4+1], u[e*4+2], u[e*4+3]);
    const float kb = -sq * INV_SQRT_DH;
    g_kb2[bh * S_ + s] = (mask[b * S_ + s] == 0) ? -1.3e16f : kb * LOG2E;
}

// ===========================================================================
// Flash attention on warp-level bf16 HMMA.  Block = (b,h) x 128-query tile.
// 8 warps x 16 query rows; Bc=64 keys/iter.  p = exp2(C1*S + kb2), no row max.
// K tile kept in both [t][d] (QK B-frags) and [d][t] (PV B-frags; V = K).
// P never leaves registers (S C-frag layout == PV A-frag layout).
// ===========================================================================
__global__ __launch_bounds__(256, 2) void attn_kernel()
{
    __shared__ __align__(16) __nv_bfloat16 sKtd[2][64][72];  // [t][d]
    __shared__ __align__(16) __nv_bfloat16 sKdt[2][64][72];  // [d][t]
    __shared__ float kb_sm[2][64];

    const int tid = threadIdx.x;
    const int wid = tid >> 5, lane = tid & 31;
    const int lg = lane >> 2;        // fragment row group 0..7
    const int qc = (lane & 3) * 2;   // fragment col pair base
    const int qt = blockIdx.x;
    const int bh = blockIdx.y;
    const int b = bh >> 4, h = bh & 15;
    const __nv_bfloat16* Qbf = g_Qbf + (size_t)bh * S_ * DH_;
    const float* kb2 = g_kb2 + bh * S_;

    // Q A-fragments (held in registers for all iterations)
    const int r0 = qt * 128 + wid * 16 + lg;
    uint32_t qa[4][4];
#pragma unroll
    for (int k = 0; k < 4; k++) {
        qa[k][0] = *(const uint32_t*)&Qbf[(size_t)r0 * DH_ + k * 16 + qc];
        qa[k][1] = *(const uint32_t*)&Qbf[(size_t)(r0 + 8) * DH_ + k * 16 + qc];
        qa[k][2] = *(const uint32_t*)&Qbf[(size_t)r0 * DH_ + k * 16 + qc + 8];
        qa[k][3] = *(const uint32_t*)&Qbf[(size_t)(r0 + 8) * DH_ + k * 16 + qc + 8];
    }

    // K loader mapping: row t = tid>>2, d block = (tid&3)*16 (32B per thread)
    const int lt = tid >> 2, ldd = (tid & 3) * 16;

    // Prologue: stage K(0), kb(0) into buffer 0
    {
        const __nv_bfloat16* src = Qbf + (size_t)lt * DH_ + ldd;
        uint4 v0 = *(const uint4*)src;
        uint4 v1 = *(const uint4*)(src + 8);
        *(uint4*)&sKtd[0][lt][ldd]     = v0;
        *(uint4*)&sKtd[0][lt][ldd + 8] = v1;
        const __nv_bfloat16* e0 = (const __nv_bfloat16*)&v0;
        const __nv_bfloat16* e1 = (const __nv_bfloat16*)&v1;
#pragma unroll
        for (int i = 0; i < 8; i++) {
            sKdt[0][ldd + i][lt]     = e0[i];
            sKdt[0][ldd + 8 + i][lt] = e1[i];
        }
        if (tid < 64) kb_sm[0][tid] = kb2[tid];
    }
    __syncthreads();

    float lacc0 = 0.0f, lacc1 = 0.0f;
    float oacc[8][4] = {};

    for (int kt = 0; kt < NKT64; kt++) {
        const int buf = kt & 1;
        const bool pf = (kt + 1 < NKT64);
        uint4 v0, v1;
        float kbv = 0.0f;
        if (pf) {
            const __nv_bfloat16* src = Qbf + (size_t)((kt + 1) * 64 + lt) * DH_ + ldd;
            v0 = *(const uint4*)src;
            v1 = *(const uint4*)(src + 8);
            if (tid < 64) kbv = kb2[(kt + 1) * 64 + tid];
        }

        // ---- S = Q @ K^T : 8 n-tiles (8 keys each) x 4 k-steps ----
        float sc[8][4];
#pragma unroll
        for (int nt = 0; nt < 8; nt++) {
            sc[nt][0] = sc[nt][1] = sc[nt][2] = sc[nt][3] = 0.0f;
#pragma unroll
            for (int k = 0; k < 4; k++) {
                uint32_t b0 = *(const uint32_t*)&sKtd[buf][nt * 8 + lg][k * 16 + qc];
                uint32_t b1 = *(const uint32_t*)&sKtd[buf][nt * 8 + lg][k * 16 + qc + 8];
                mma16816(sc[nt], qa[k], b0, b1);
            }
        }

        // ---- softmax: p = exp2(C1*s + kb2[t]); accumulate l; pack bf16 ----
        uint32_t pk[8][2];
#pragma unroll
        for (int nt = 0; nt < 8; nt++) {
            float2 kbp = *(const float2*)&kb_sm[buf][nt * 8 + qc];
            float p0 = ex2f(fmaf(sc[nt][0], C1, kbp.x));
            float p1 = ex2f(fmaf(sc[nt][1], C1, kbp.y));
            float p2 = ex2f(fmaf(sc[nt][2], C1, kbp.x));
            float p3 = ex2f(fmaf(sc[nt][3], C1, kbp.y));
            lacc0 += p0 + p1;
            lacc1 += p2 + p3;
            pk[nt][0] = packbf2(p0, p1);
            pk[nt][1] = packbf2(p2, p3);
        }

        // ---- O += P @ K : A-frags from pk (C layout == A layout trick) ----
#pragma unroll
        for (int tk = 0; tk < 4; tk++) {
            uint32_t pa[4] = {pk[2 * tk][0], pk[2 * tk][1],
                              pk[2 * tk + 1][0], pk[2 * tk + 1][1]};
#pragma unroll
            for (int nt = 0; nt < 8; nt++) {
                uint32_t b0 = *(const uint32_t*)&sKdt[buf][nt * 8 + lg][tk * 16 + qc];
                uint32_t b1 = *(const uint32_t*)&sKdt[buf][nt * 8 + lg][tk * 16 + qc + 8];
                mma16816(oacc[nt], pa, b0, b1);
            }
        }

        // ---- commit prefetched K(kt+1) into the other buffer ----
        if (pf) {
            const int nb = buf ^ 1;
            *(uint4*)&sKtd[nb][lt][ldd]     = v0;
            *(uint4*)&sKtd[nb][lt][ldd + 8] = v1;
            const __nv_bfloat16* e0 = (const __nv_bfloat16*)&v0;
            const __nv_bfloat16* e1 = (const __nv_bfloat16*)&v1;
#pragma unroll
            for (int i = 0; i < 8; i++) {
                sKdt[nb][ldd + i][lt]     = e0[i];
                sKdt[nb][ldd + 8 + i][lt] = e1[i];
            }
            if (tid < 64) kb_sm[nb][tid] = kbv;
        }
        __syncthreads();
    }

    // ---- epilogue: O / l -> g_attn ----
    lacc0 += __shfl_xor_sync(0xffffffffu, lacc0, 1);
    lacc0 += __shfl_xor_sync(0xffffffffu, lacc0, 2);
    lacc1 += __shfl_xor_sync(0xffffffffu, lacc1, 1);
    lacc1 += __shfl_xor_sync(0xffffffffu, lacc1, 2);
    const float inv0 = 1.0f / lacc0;
    const float inv1 = 1.0f / lacc1;

    const size_t grow0 = (size_t)(b * S_ + qt * 128 + wid * 16 + lg) * D_ + h * DH_;
    const size_t grow1 = grow0 + 8 * D_;
#pragma unroll
    for (int nt = 0; nt < 8; nt++) {
        const int d = nt * 8 + qc;
        *(float2*)&g_attn[grow0 + d] = make_float2(oacc[nt][0] * inv0, oacc[nt][1] * inv0);
        *(float2*)&g_attn[grow1 + d] = make_float2(oacc[nt][2] * inv1, oacc[nt][3] * inv1);
    }
}

// ===========================================================================
// Launch
// ===========================================================================
extern "C" void kernel_launch(void* const* d_in, const int* in_sizes, int n_in,
                              void* d_out, int out_size)
{
    // metadata order: x, W_q, b_q, W_v, W_out, b_out, mask
    const float* x     = (const float*)d_in[0];
    const float* W_q   = (const float*)d_in[1];
    const float* b_q   = (const float*)d_in[2];
    const float* W_v   = (const float*)d_in[3];
    const float* W_out = (const float*)d_in[4];
    const float* b_out = (const float*)d_in[5];
    const int*   mask  = (const int*)d_in[6];
    float* out = (float*)d_out;

    float *pQ, *pA, *pWt;
    cudaGetSymbolAddress((void**)&pQ,  g_Q);
    cudaGetSymbolAddress((void**)&pA,  g_attn);
    cudaGetSymbolAddress((void**)&pWt, g_Wt);

    dim3 gge(D_ / 128, BS_ / 128);

    // 1) Q = x @ W_q^T + b_q (bf16 tensor cores, fp32 accum)
    gemm_bf16<false><<<gge, 256>>>(x, W_q, b_q, nullptr, pQ, BS_, D_, D_);

    // 2) bf16 head-major Q + per-key bias
    convert_q_kernel<<<(BS_ * H_) / 256, 256>>>(mask);

    // 3) per-head M, folded into W_out
    compute_M_kernel<<<H_, 256>>>(W_q, W_v);
    fold_wout_kernel<<<H_ * (D_ / 64), 256>>>(W_out);

    // 4) attention (warp-level bf16 HMMA flash)
    attn_kernel<<<dim3(S_ / 128, B_ * H_), 256>>>();

    // 5) out = x + (O/l) @ Wt^T + b_out  (bf16 tensor cores)
    gemm_bf16<true><<<gge, 256>>>(pA, pWt, b_out, x, out, BS_, D_, D_);
}

// round 17
// speedup vs baseline: 2.1240x; 1.1366x over previous
#include <cuda_runtime.h>
#include <cuda_bf16.h>
#include <cstdint>
#include <math.h>

// Problem constants
#define B_ 2
#define S_ 2048
#define D_ 1024
#define H_ 16
#define DH_ 64
#define BS_ (B_ * S_)
#define INV_SQRT_DH 0.125f
#define NKT64 (S_ / 64)         // 32 key tiles of 64
#define C1 0.3606738f           // 0.25 * log2(e)  (score scale folded into exp2)
#define LOG2E 1.4426950f

// Scratch (device globals: no runtime allocation allowed)
__device__ float g_Q[BS_ * D_];            // q projection fp32, [B,S,H,DH]
__device__ __nv_bfloat16 g_Qbf[BS_ * D_];  // q bf16, head-major [B,H,S,DH]
__device__ float g_attn[BS_ * D_];         // O/l, [B,S,H,DH]
__device__ float g_M[H_ * DH_ * DH_];      // per-head 64x64 (incl. 1/sqrt(dh))
__device__ float g_Wt[D_ * D_];            // folded W_out @ M  ([n][h*64+d])
__device__ float g_kb2[B_ * H_ * S_];      // log2e * (mask ? -||q_t||^2/8 : -9e15)

// ===========================================================================
// Warp-level bf16 MMA + helpers (sm_80+ PTX; HMMA pipe on sm_103)
// ===========================================================================
__device__ __forceinline__ void mma16816(float c[4], const uint32_t a[4],
                                         uint32_t b0, uint32_t b1) {
    asm volatile(
        "mma.sync.aligned.m16n8k16.row.col.f32.bf16.bf16.f32 "
        "{%0,%1,%2,%3}, {%4,%5,%6,%7}, {%8,%9}, {%0,%1,%2,%3};"
        : "+f"(c[0]), "+f"(c[1]), "+f"(c[2]), "+f"(c[3])
        : "r"(a[0]), "r"(a[1]), "r"(a[2]), "r"(a[3]), "r"(b0), "r"(b1));
}
__device__ __forceinline__ float ex2f(float x) {
    float r;
    asm("ex2.approx.f32 %0, %1;" : "=f"(r) : "f"(x));
    return r;
}
__device__ __forceinline__ uint32_t packbf2(float x, float y) {
    __nv_bfloat162 p = __floats2bfloat162_rn(x, y);
    return *(uint32_t*)&p;
}
__device__ __forceinline__ uint32_t smem_u32(const void* p) {
    uint32_t a;
    asm("{ .reg .u64 t; cvta.to.shared.u64 t, %1; cvt.u32.u64 %0, t; }" : "=r"(a) : "l"(p));
    return a;
}
__device__ __forceinline__ void ldmx4(uint32_t r[4], uint32_t addr) {
    asm volatile("ldmatrix.sync.aligned.m8n8.x4.shared.b16 {%0,%1,%2,%3}, [%4];"
                 : "=r"(r[0]), "=r"(r[1]), "=r"(r[2]), "=r"(r[3]) : "r"(addr));
}
__device__ __forceinline__ void ldmx4t(uint32_t r[4], uint32_t addr) {
    asm volatile("ldmatrix.sync.aligned.m8n8.x4.trans.shared.b16 {%0,%1,%2,%3}, [%4];"
                 : "=r"(r[0]), "=r"(r[1]), "=r"(r[2]), "=r"(r[3]) : "r"(addr));
}
__device__ __forceinline__ void ldmx2(uint32_t& r0, uint32_t& r1, uint32_t addr) {
    asm volatile("ldmatrix.sync.aligned.m8n8.x2.shared.b16 {%0,%1}, [%2];"
                 : "=r"(r0), "=r"(r1) : "r"(addr));
}

// ===========================================================================
// bf16 tensor-core GEMM: C = A @ W^T + bias (+R).  A:[M,K], W:[N,K] fp32.
// 128x128 tile, BK=16, 256 threads (8 warps = 2m x 4n), warp tile 64x32.
// fp32 gmem -> bf16 smem inline. Stride 24 bf16 => conflict-free ldmatrix.
// ===========================================================================
#define GSTR 24
#define GBUF (128 * GSTR * 2)   // bytes per buffer per matrix

template <bool RESID>
__global__ __launch_bounds__(256, 2) void gemm_bf16(
    const float* __restrict__ A, const float* __restrict__ W,
    const float* __restrict__ bias, const float* __restrict__ R,
    float* __restrict__ C, int M, int N, int K)
{
    __shared__ __align__(16) __nv_bfloat16 As[2][128][GSTR];
    __shared__ __align__(16) __nv_bfloat16 Ws[2][128][GSTR];

    const int tid = threadIdx.x, lane = tid & 31, wid = tid >> 5;
    const int wm = (wid >> 2) * 64, wn = (wid & 3) * 32;
    const int lg = lane >> 2, qc = (lane & 3) * 2;
    const int m0 = blockIdx.y * 128, n0 = blockIdx.x * 128;
    const int lrow = tid >> 1, lpart = (tid & 1) * 8;   // loader: half-row each

    const uint32_t aSm = smem_u32(&As[0][0][0]);
    const uint32_t bSm = smem_u32(&Ws[0][0][0]);
    const uint32_t aFrag = aSm + (uint32_t)(((wm + (lane & 15)) * GSTR + (lane >> 4) * 8) * 2);
    const uint32_t bFrag = bSm + (uint32_t)(((wn + (lane & 7)) * GSTR + ((lane >> 3) & 1) * 8) * 2);

    // ---- preload tile 0 ----
    {
        const float* ap = &A[(size_t)(m0 + lrow) * K + lpart];
        const float* wp = &W[(size_t)(n0 + lrow) * K + lpart];
        float4 a0 = *(const float4*)ap, a1 = *(const float4*)(ap + 4);
        float4 w0 = *(const float4*)wp, w1 = *(const float4*)(wp + 4);
        *(uint4*)&As[0][lrow][lpart] = make_uint4(packbf2(a0.x, a0.y), packbf2(a0.z, a0.w),
                                                  packbf2(a1.x, a1.y), packbf2(a1.z, a1.w));
        *(uint4*)&Ws[0][lrow][lpart] = make_uint4(packbf2(w0.x, w0.y), packbf2(w0.z, w0.w),
                                                  packbf2(w1.x, w1.y), packbf2(w1.z, w1.w));
    }
    __syncthreads();

    float acc[4][4][4] = {};   // [mt][nt][frag]
    const int nk = K / 16;
    for (int t = 0; t < nk; t++) {
        const int buf = t & 1;
        float4 a0, a1, w0, w1;
        const bool pf = (t + 1 < nk);
        if (pf) {
            const float* ap = &A[(size_t)(m0 + lrow) * K + (t + 1) * 16 + lpart];
            const float* wp = &W[(size_t)(n0 + lrow) * K + (t + 1) * 16 + lpart];
            a0 = *(const float4*)ap; a1 = *(const float4*)(ap + 4);
            w0 = *(const float4*)wp; w1 = *(const float4*)(wp + 4);
        }

        uint32_t af[4][4];
#pragma unroll
        for (int mt = 0; mt < 4; mt++)
            ldmx4(af[mt], aFrag + buf * GBUF + mt * (16 * GSTR * 2));
        uint32_t bf[4][2];
#pragma unroll
        for (int nt = 0; nt < 4; nt++)
            ldmx2(bf[nt][0], bf[nt][1], bFrag + buf * GBUF + nt * (8 * GSTR * 2));
#pragma unroll
        for (int mt = 0; mt < 4; mt++)
#pragma unroll
            for (int nt = 0; nt < 4; nt++)
                mma16816(acc[mt][nt], af[mt], bf[nt][0], bf[nt][1]);

        if (pf) {
            const int nb = buf ^ 1;
            *(uint4*)&As[nb][lrow][lpart] = make_uint4(packbf2(a0.x, a0.y), packbf2(a0.z, a0.w),
                                                       packbf2(a1.x, a1.y), packbf2(a1.z, a1.w));
            *(uint4*)&Ws[nb][lrow][lpart] = make_uint4(packbf2(w0.x, w0.y), packbf2(w0.z, w0.w),
                                                       packbf2(w1.x, w1.y), packbf2(w1.z, w1.w));
        }
        __syncthreads();
    }

    // ---- epilogue ----
#pragma unroll
    for (int nt = 0; nt < 4; nt++) {
        const int col = n0 + wn + nt * 8 + qc;
        const float2 b2 = *(const float2*)&bias[col];
#pragma unroll
        for (int mt = 0; mt < 4; mt++) {
            const int row = m0 + wm + mt * 16 + lg;
            float2 o0 = make_float2(acc[mt][nt][0] + b2.x, acc[mt][nt][1] + b2.y);
            float2 o1 = make_float2(acc[mt][nt][2] + b2.x, acc[mt][nt][3] + b2.y);
            if (RESID) {
                float2 r0 = *(const float2*)&R[(size_t)row * N + col];
                float2 r1 = *(const float2*)&R[(size_t)(row + 8) * N + col];
                o0.x += r0.x; o0.y += r0.y; o1.x += r1.x; o1.y += r1.y;
            }
            *(float2*)&C[(size_t)row * N + col]       = o0;
            *(float2*)&C[(size_t)(row + 8) * N + col] = o1;
        }
    }
}

// ===========================================================================
// M_h[d][f] = sum_e W_q[e, h*64+d] * W_v[e, h*64+f] * 0.125
// ===========================================================================
__global__ __launch_bounds__(256) void compute_M_kernel(
    const float* __restrict__ Wq, const float* __restrict__ Wv)
{
    __shared__ float Aq[32][68];
    __shared__ float Av[32][68];
    const int h = blockIdx.x;
    const int tid = threadIdx.x;
    const int tx = tid & 15, ty = tid >> 4;

    float acc[4][4] = {};
    for (int e0 = 0; e0 < D_; e0 += 32) {
#pragma unroll
        for (int e = 0; e < 8; e++) {
            int idx = tid + e * 256;
            int ee = idx >> 6, c = idx & 63;
            Aq[ee][c] = Wq[(size_t)(e0 + ee) * D_ + h * DH_ + c];
            Av[ee][c] = Wv[(size_t)(e0 + ee) * D_ + h * DH_ + c];
        }
        __syncthreads();
#pragma unroll
        for (int ee = 0; ee < 32; ee++) {
            float4 a4 = *(const float4*)&Aq[ee][ty * 4];
            float4 b4 = *(const float4*)&Av[ee][tx * 4];
            float av[4] = {a4.x, a4.y, a4.z, a4.w};
            float bv[4] = {b4.x, b4.y, b4.z, b4.w};
#pragma unroll
            for (int i = 0; i < 4; i++)
#pragma unroll
                for (int j = 0; j < 4; j++) acc[i][j] += av[i] * bv[j];
        }
        __syncthreads();
    }
#pragma unroll
    for (int i = 0; i < 4; i++)
#pragma unroll
        for (int j = 0; j < 4; j++)
            g_M[h * DH_ * DH_ + (ty * 4 + i) * DH_ + tx * 4 + j] = acc[i][j] * INV_SQRT_DH;
}

// ===========================================================================
// Fold: Wt[n, h*64+d] = sum_f W_out[n, h*64+f] * M_h[d][f]
// Block = (h, 64 n-rows). Smem-tiled 64x64x64 mini-GEMM, 4x4 microtile.
// ===========================================================================
__global__ __launch_bounds__(256) void fold_wout_kernel(const float* __restrict__ Wout)
{
    __shared__ float Wb[64][68];    // [f][n]  (transposed stage)
    __shared__ float Msm[64][68];   // [f][d]
    const int h = blockIdx.x & 15;
    const int n0 = (blockIdx.x >> 4) * 64;
    const int tid = threadIdx.x;
    const int tx = tid & 15, ty = tid >> 4;

    // Stage: row r = tid>>2, quad group (tid&3)*16; float4 reads, transposed scatter
    {
        const int r = tid >> 2, cg = (tid & 3) * 16;
        const float* wsrc = Wout + (size_t)(n0 + r) * D_ + h * 64 + cg;
        const float* msrc = g_M + h * 4096 + r * 64 + cg;   // M[d=r][f=cg..]
#pragma unroll
        for (int e = 0; e < 4; e++) {
            float4 wv = *(const float4*)(wsrc + e * 4);
            float4 mv = *(const float4*)(msrc + e * 4);
            const int c = cg + e * 4;
            Wb[c + 0][r] = wv.x; Wb[c + 1][r] = wv.y;
            Wb[c + 2][r] = wv.z; Wb[c + 3][r] = wv.w;
            Msm[c + 0][r] = mv.x; Msm[c + 1][r] = mv.y;
            Msm[c + 2][r] = mv.z; Msm[c + 3][r] = mv.w;
        }
    }
    __syncthreads();

    float acc[4][4] = {};
#pragma unroll
    for (int f = 0; f < 64; f++) {
        float4 a4 = *(const float4*)&Wb[f][ty * 4];
        float4 b4 = *(const float4*)&Msm[f][tx * 4];
        float av[4] = {a4.x, a4.y, a4.z, a4.w};
        float bv[4] = {b4.x, b4.y, b4.z, b4.w};
#pragma unroll
        for (int i = 0; i < 4; i++)
#pragma unroll
            for (int j = 0; j < 4; j++) acc[i][j] = fmaf(av[i], bv[j], acc[i][j]);
    }
#pragma unroll
    for (int i = 0; i < 4; i++)
        *(float4*)&g_Wt[(size_t)(n0 + ty * 4 + i) * D_ + h * 64 + tx * 4] =
            make_float4(acc[i][0], acc[i][1], acc[i][2], acc[i][3]);
}

// ===========================================================================
// Convert: g_Q [B,S,H,DH] fp32 -> g_Qbf [B,H,S,DH] bf16; kb2 = log2e * bias
// ===========================================================================
__global__ __launch_bounds__(256) void convert_q_kernel(const int* __restrict__ mask)
{
    const int idx = blockIdx.x * 256 + threadIdx.x;   // 0..65535
    const int s = idx & (S_ - 1);
    const int bh = idx >> 11;
    const int b = bh >> 4, h = bh & 15;
    const float* src = g_Q + (size_t)(b * S_ + s) * D_ + h * DH_;
    float sq = 0.0f;
    uint32_t u[32];
#pragma unroll
    for (int j = 0; j < 64; j += 4) {
        float4 v = *(const float4*)&src[j];
        sq += v.x * v.x + v.y * v.y + v.z * v.z + v.w * v.w;
        u[j / 2]     = packbf2(v.x, v.y);
        u[j / 2 + 1] = packbf2(v.z, v.w);
    }
    uint4* dst = (uint4*)(g_Qbf + (size_t)(bh * S_ + s) * DH_);
#pragma unroll
    for (int e = 0; e < 8; e++)
        dst[e] = make_uint4(u[e*4], u[e*4+1], u[e*4+2], u[e*4+3]);
    const float kb = -sq * INV_SQRT_DH;
    g_kb2[bh * S_ + s] = (mask[b * S_ + s] == 0) ? -1.3e16f : kb * LOG2E;
}

// ===========================================================================
// Flash attention on warp-level bf16 HMMA.  Block = (b,h) x 128-query tile.
// 8 warps x 16 query rows; Bc=64 keys/iter.  p = exp2(C1*S + kb2), no row max.
// SINGLE K tile [t][d] (stride 72): QK B-frags via ldmatrix, PV B-frags via
// ldmatrix.trans (V = K).  P never leaves registers.
// ===========================================================================
#define KSTR 72
#define KROWB (KSTR * 2)            // 144 bytes per row
#define KBUF (64 * KROWB)           // 9216 bytes per buffer

__global__ __launch_bounds__(256, 2) void attn_kernel()
{
    __shared__ __align__(16) __nv_bfloat16 sK[2][64][KSTR];
    __shared__ float kb_sm[2][64];

    const int tid = threadIdx.x;
    const int wid = tid >> 5, lane = tid & 31;
    const int lg = lane >> 2;        // fragment row group 0..7
    const int qc = (lane & 3) * 2;   // fragment col pair base
    const int qt = blockIdx.x;
    const int bh = blockIdx.y;
    const int b = bh >> 4, h = bh & 15;
    const __nv_bfloat16* Qbf = g_Qbf + (size_t)bh * S_ * DH_;
    const float* kb2 = g_kb2 + bh * S_;

    // Q A-fragments (held in registers for all iterations)
    const int r0 = qt * 128 + wid * 16 + lg;
    uint32_t qa[4][4];
#pragma unroll
    for (int k = 0; k < 4; k++) {
        qa[k][0] = *(const uint32_t*)&Qbf[(size_t)r0 * DH_ + k * 16 + qc];
        qa[k][1] = *(const uint32_t*)&Qbf[(size_t)(r0 + 8) * DH_ + k * 16 + qc];
        qa[k][2] = *(const uint32_t*)&Qbf[(size_t)r0 * DH_ + k * 16 + qc + 8];
        qa[k][3] = *(const uint32_t*)&Qbf[(size_t)(r0 + 8) * DH_ + k * 16 + qc + 8];
    }

    // ldmatrix lane base addresses
    const uint32_t kBase = smem_u32(&sK[0][0][0]);
    // QK (normal): 8x8 tiles, rows = t, cols = d;  4 matrices = d-cols {0,8,16,24}
    const uint32_t aQK = kBase + (uint32_t)((lane & 7) * KROWB + (lane >> 3) * 16);
    // PV (trans): matrices = {t0..t0+7}x{d0..+7}, {t0+8..15}x{d0..+7}, same +8 cols
    const uint32_t aPV = kBase + (uint32_t)((lane & 15) * KROWB + (lane >> 4) * 16);

    // K loader mapping: row t = tid>>2, d block = (tid&3)*16 (32B per thread)
    const int lt = tid >> 2, ldd = (tid & 3) * 16;

    // Prologue: stage K(0), kb(0) into buffer 0
    {
        const __nv_bfloat16* src = Qbf + (size_t)lt * DH_ + ldd;
        *(uint4*)&sK[0][lt][ldd]     = *(const uint4*)src;
        *(uint4*)&sK[0][lt][ldd + 8] = *(const uint4*)(src + 8);
        if (tid < 64) kb_sm[0][tid] = kb2[tid];
    }
    __syncthreads();

    float lacc0 = 0.0f, lacc1 = 0.0f;
    float oacc[8][4] = {};

    for (int kt = 0; kt < NKT64; kt++) {
        const int buf = kt & 1;
        const uint32_t bofs = (uint32_t)buf * KBUF;
        const bool pf = (kt + 1 < NKT64);
        uint4 v0, v1;
        float kbv = 0.0f;
        if (pf) {
            const __nv_bfloat16* src = Qbf + (size_t)((kt + 1) * 64 + lt) * DH_ + ldd;
            v0 = *(const uint4*)src;
            v1 = *(const uint4*)(src + 8);
            if (tid < 64) kbv = kb2[(kt + 1) * 64 + tid];
        }

        // ---- S = Q @ K^T : per nt, 2x ldmatrix.x4 + 4 MMAs ----
        float sc[8][4];
#pragma unroll
        for (int nt = 0; nt < 8; nt++) {
            uint32_t bq0[4], bq1[4];
            ldmx4(bq0, aQK + bofs + nt * (8 * KROWB));
            ldmx4(bq1, aQK + bofs + nt * (8 * KROWB) + 64);
            sc[nt][0] = sc[nt][1] = sc[nt][2] = sc[nt][3] = 0.0f;
            mma16816(sc[nt], qa[0], bq0[0], bq0[1]);
            mma16816(sc[nt], qa[1], bq0[2], bq0[3]);
            mma16816(sc[nt], qa[2], bq1[0], bq1[1]);
            mma16816(sc[nt], qa[3], bq1[2], bq1[3]);
        }

        // ---- softmax: p = exp2(C1*s + kb2[t]); accumulate l; pack bf16 ----
        uint32_t pk[8][2];
#pragma unroll
        for (int nt = 0; nt < 8; nt++) {
            float2 kbp = *(const float2*)&kb_sm[buf][nt * 8 + qc];
            float p0 = ex2f(fmaf(sc[nt][0], C1, kbp.x));
            float p1 = ex2f(fmaf(sc[nt][1], C1, kbp.y));
            float p2 = ex2f(fmaf(sc[nt][2], C1, kbp.x));
            float p3 = ex2f(fmaf(sc[nt][3], C1, kbp.y));
            lacc0 += p0 + p1;
            lacc1 += p2 + p3;
            pk[nt][0] = packbf2(p0, p1);
            pk[nt][1] = packbf2(p2, p3);
        }

        // ---- O += P @ K : PV B-frags via ldmatrix.trans on the same tile ----
#pragma unroll
        for (int tk = 0; tk < 4; tk++) {
            uint32_t pa[4] = {pk[2 * tk][0], pk[2 * tk][1],
                              pk[2 * tk + 1][0], pk[2 * tk + 1][1]};
#pragma unroll
            for (int np = 0; np < 4; np++) {
                uint32_t bt[4];
                ldmx4t(bt, aPV + bofs + tk * (16 * KROWB) + np * 32);
                mma16816(oacc[2 * np],     pa, bt[0], bt[1]);
                mma16816(oacc[2 * np + 1], pa, bt[2], bt[3]);
            }
        }

        // ---- commit prefetched K(kt+1) into the other buffer ----
        if (pf) {
            const int nb = buf ^ 1;
            *(uint4*)&sK[nb][lt][ldd]     = v0;
            *(uint4*)&sK[nb][lt][ldd + 8] = v1;
            if (tid < 64) kb_sm[nb][tid] = kbv;
        }
        __syncthreads();
    }

    // ---- epilogue: O / l -> g_attn ----
    lacc0 += __shfl_xor_sync(0xffffffffu, lacc0, 1);
    lacc0 += __shfl_xor_sync(0xffffffffu, lacc0, 2);
    lacc1 += __shfl_xor_sync(0xffffffffu, lacc1, 1);
    lacc1 += __shfl_xor_sync(0xffffffffu, lacc1, 2);
    const float inv0 = 1.0f / lacc0;
    const float inv1 = 1.0f / lacc1;

    const size_t grow0 = (size_t)(b * S_ + qt * 128 + wid * 16 + lg) * D_ + h * DH_;
    const size_t grow1 = grow0 + 8 * D_;
#pragma unroll
    for (int nt = 0; nt < 8; nt++) {
        const int d = nt * 8 + qc;
        *(float2*)&g_attn[grow0 + d] = make_float2(oacc[nt][0] * inv0, oacc[nt][1] * inv0);
        *(float2*)&g_attn[grow1 + d] = make_float2(oacc[nt][2] * inv1, oacc[nt][3] * inv1);
    }
}

// ===========================================================================
// Launch
// ===========================================================================
extern "C" void kernel_launch(void* const* d_in, const int* in_sizes, int n_in,
                              void* d_out, int out_size)
{
    // metadata order: x, W_q, b_q, W_v, W_out, b_out, mask
    const float* x     = (const float*)d_in[0];
    const float* W_q   = (const float*)d_in[1];
    const float* b_q   = (const float*)d_in[2];
    const float* W_v   = (const float*)d_in[3];
    const float* W_out = (const float*)d_in[4];
    const float* b_out = (const float*)d_in[5];
    const int*   mask  = (const int*)d_in[6];
    float* out = (float*)d_out;

    float *pQ, *pA, *pWt;
    cudaGetSymbolAddress((void**)&pQ,  g_Q);
    cudaGetSymbolAddress((void**)&pA,  g_attn);
    cudaGetSymbolAddress((void**)&pWt, g_Wt);

    dim3 gge(D_ / 128, BS_ / 128);

    // 1) Q = x @ W_q^T + b_q (bf16 tensor cores, fp32 accum)
    gemm_bf16<false><<<gge, 256>>>(x, W_q, b_q, nullptr, pQ, BS_, D_, D_);

    // 2) bf16 head-major Q + per-key bias
    convert_q_kernel<<<(BS_ * H_) / 256, 256>>>(mask);

    // 3) per-head M, folded into W_out
    compute_M_kernel<<<H_, 256>>>(W_q, W_v);
    fold_wout_kernel<<<H_ * (D_ / 64), 256>>>(W_out);

    // 4) attention (warp-level bf16 HMMA flash, ldmatrix fragments)
    attn_kernel<<<dim3(S_ / 128, B_ * H_), 256>>>();

    // 5) out = x + (O/l) @ Wt^T + b_out  (bf16 tensor cores)
    gemm_bf16<true><<<gge, 256>>>(pA, pWt, b_out, x, out, BS_, D_, D_);
}